// round 1
// baseline (speedup 1.0000x reference)
#include <cuda_runtime.h>

// Problem constants
#define CIN    32
#define COUT   32
#define HDIM   64
#define WDIM   64
#define KKN    9
#define TILE   8          // 8x8 pixel tile per CTA
#define XT     10         // tile + halo
#define XSTR   101        // x_s row stride (per channel): 5*c mod 32 distinct -> conflict free
#define WPSTR  33         // wp_s row stride: (9c+k+c') mod 32 distinct -> conflict free
#define NTHR   256

// smem: wp_s[288][33] + x_s[32][101]
#define SMEM_FLOATS (288 * WPSTR + CIN * XSTR)

__global__ __launch_bounds__(NTHR)
void dyn_conv_kernel(const float* __restrict__ x,
                     const float* __restrict__ Wp,
                     const float* __restrict__ bp,
                     float* __restrict__ out)
{
    extern __shared__ float smem[];
    float* wp_s = smem;                  // [288][33]
    float* x_s  = smem + 288 * WPSTR;    // [32][101], first 100 entries of each row used

    const int bz  = blockIdx.z;
    const int b   = bz >> 5;             // batch
    const int o   = bz & 31;             // output channel
    const int tx0 = blockIdx.x * TILE;
    const int ty0 = blockIdx.y * TILE;
    const int tid = threadIdx.x;

    // ---- Stage Wp slice for this o: rows [o*288, o*288+288), 32 cols each ----
    {
        const float4* wpv = reinterpret_cast<const float4*>(Wp + (size_t)o * 288 * 32);
        #pragma unroll 3
        for (int i = tid; i < 288 * 8; i += NTHR) {
            int r  = i >> 3;
            int cq = i & 7;
            float4 v = wpv[i];
            float* dst = wp_s + r * WPSTR + cq * 4;
            dst[0] = v.x; dst[1] = v.y; dst[2] = v.z; dst[3] = v.w;
        }
    }

    // ---- Stage x halo tile: 32 channels x 10x10 (zero-padded at borders) ----
    {
        const float* xb = x + (size_t)b * CIN * HDIM * WDIM;
        #pragma unroll 2
        for (int i = tid; i < CIN * 100; i += NTHR) {
            int c  = i / 100;
            int rr = i - c * 100;
            int yy = ty0 + rr / 10 - 1;
            int xx = tx0 + (rr % 10) - 1;
            float v = 0.0f;
            if (yy >= 0 && yy < HDIM && xx >= 0 && xx < WDIM)
                v = xb[(c * HDIM + yy) * WDIM + xx];
            x_s[c * XSTR + rr] = v;
        }
    }
    __syncthreads();

    const int warp = tid >> 5;   // tile row (0..7)
    const int lane = tid & 31;   // lane = Cin index c

    // ---- Accumulators: dyn_w[o, c=lane, k, p] for this warp's 8 pixels ----
    float acc[KKN][TILE];
    {
        const float* bprow = bp + o * 288 + lane * KKN;
        #pragma unroll
        for (int k = 0; k < KKN; k++) {
            float bv = bprow[k];
            #pragma unroll
            for (int p = 0; p < TILE; p++) acc[k][p] = bv;
        }
    }

    // center pixel offset inside x_s row: tile coord (1+warp, 1+p)
    const int centerBase = (1 + warp) * XT + 1;
    const float* wrow = wp_s + (lane * KKN) * WPSTR;

    // ---- Mainloop: pred GEMM slice, K=32 over input channels c' ----
    for (int cp = 0; cp < CIN; cp++) {
        float xv[TILE];
        const float* xr = x_s + cp * XSTR + centerBase;
        #pragma unroll
        for (int p = 0; p < TILE; p++) xv[p] = xr[p];      // broadcast loads
        #pragma unroll
        for (int k = 0; k < KKN; k++) {
            float w = wrow[k * WPSTR + cp];                // conflict-free
            #pragma unroll
            for (int p = 0; p < TILE; p++)
                acc[k][p] = fmaf(w, xv[p], acc[k][p]);
        }
    }

    // ---- Normalize over Cin (= lanes): butterfly all-reduce of squares ----
    #pragma unroll
    for (int k = 0; k < KKN; k++) {
        #pragma unroll
        for (int p = 0; p < TILE; p++) {
            float s = acc[k][p] * acc[k][p];
            s += __shfl_xor_sync(0xffffffffu, s, 16);
            s += __shfl_xor_sync(0xffffffffu, s, 8);
            s += __shfl_xor_sync(0xffffffffu, s, 4);
            s += __shfl_xor_sync(0xffffffffu, s, 2);
            s += __shfl_xor_sync(0xffffffffu, s, 1);
            // v / max(sqrt(s),1e-12) == v * rsqrt(max(s,1e-24))
            acc[k][p] *= rsqrtf(fmaxf(s, 1e-24f));
        }
    }

    // ---- Per-lane norm over k, patch contraction, dynamic bias, reduce ----
    const float wpb  = Wp[(size_t)(9216 + o) * 32 + lane]; // dyn-bias predictor row
    const float bpo  = bp[9216 + o];
    const float* xlane = x_s + lane * XSTR;

    #pragma unroll
    for (int p = 0; p < TILE; p++) {
        float s = 0.0f;
        #pragma unroll
        for (int k = 0; k < KKN; k++) s = fmaf(acc[k][p], acc[k][p], s);
        float inv2 = rsqrtf(fmaxf(s, 1e-24f));

        // dynamic bias partial: Wp[9216+o, lane] * x[lane, pixel]
        float t = wpb * xlane[centerBase + p];

        #pragma unroll
        for (int k = 0; k < KKN; k++) {
            int dy = k / 3, dx = k % 3;
            float pv = xlane[(warp + dy) * XT + (p + dx)]; // patch value, conflict-free
            t = fmaf(acc[k][p] * inv2, pv, t);
        }
        t += __shfl_xor_sync(0xffffffffu, t, 16);
        t += __shfl_xor_sync(0xffffffffu, t, 8);
        t += __shfl_xor_sync(0xffffffffu, t, 4);
        t += __shfl_xor_sync(0xffffffffu, t, 2);
        t += __shfl_xor_sync(0xffffffffu, t, 1);
        if (lane == 0) {
            int yy = ty0 + warp;
            int xx = tx0 + p;
            out[(((size_t)b * COUT + o) * HDIM + yy) * WDIM + xx] = t + bpo;
        }
    }
}

extern "C" void kernel_launch(void* const* d_in, const int* in_sizes, int n_in,
                              void* d_out, int out_size)
{
    const float* x  = (const float*)d_in[0];   // (2, 32, 64, 64)
    const float* Wp = (const float*)d_in[1];   // (9248, 32)
    const float* bp = (const float*)d_in[2];   // (9248,)
    float* out = (float*)d_out;                // (2, 32, 64, 64)

    const size_t smem_bytes = SMEM_FLOATS * sizeof(float); // 50,944 B > 48K default
    cudaFuncSetAttribute(dyn_conv_kernel,
                         cudaFuncAttributeMaxDynamicSharedMemorySize,
                         (int)smem_bytes);

    dim3 grid(WDIM / TILE, HDIM / TILE, 2 * COUT);  // (8, 8, 64)
    dyn_conv_kernel<<<grid, NTHR, smem_bytes>>>(x, Wp, bp, out);
}

// round 2
// speedup vs baseline: 1.0844x; 1.0844x over previous
#include <cuda_runtime.h>

// Problem constants
#define CIN    32
#define COUT   32
#define HDIM   64
#define WDIM   64
#define KKN    9
#define TILE   8           // 8x8 pixel tile per CTA
#define NTHR   256

// Weight smem: wp_dup[cp][288 pairs {w,w}] row stride 578 words (8B-aligned, conflict-free)
#define WPSTR  578
// x smem: per channel 10 rows x 12 words, channel stride 122 (even -> float2 aligned; 2-way epi conflicts)
#define XROW   12
#define CSTR   122

#define SMEM_FLOATS (CIN * WPSTR + CIN * CSTR)   // 18496 + 3904 = 22400 words = 89.6 KB

__device__ __forceinline__ unsigned long long pack2(float lo, float hi) {
    unsigned long long r;
    asm("mov.b64 %0, {%1, %2};" : "=l"(r) : "f"(lo), "f"(hi));
    return r;
}
__device__ __forceinline__ void unpack2(unsigned long long v, float& lo, float& hi) {
    asm("mov.b64 {%0, %1}, %2;" : "=f"(lo), "=f"(hi) : "l"(v));
}
#define FFMA2(d, a, b, c) \
    asm("fma.rn.f32x2 %0, %1, %2, %3;" : "=l"(d) : "l"(a), "l"(b), "l"(c))
#define FMUL2(d, a, b) \
    asm("mul.rn.f32x2 %0, %1, %2;" : "=l"(d) : "l"(a), "l"(b))

__global__ __launch_bounds__(NTHR)
void dyn_conv_kernel(const float* __restrict__ x,
                     const float* __restrict__ Wp,
                     const float* __restrict__ bp,
                     float* __restrict__ out)
{
    extern __shared__ float smem[];
    float* wp_s = smem;                   // duplicated weight pairs
    float* x_s  = smem + CIN * WPSTR;     // x halo tile

    const int bz  = blockIdx.z;
    const int b   = bz >> 5;              // batch
    const int o   = bz & 31;              // output channel
    const int tx0 = blockIdx.x * TILE;
    const int ty0 = blockIdx.y * TILE;
    const int tid = threadIdx.x;

    // ---- Stage Wp slice for this o, duplicated {w,w}: wp_s[cp*578 + j*2 .. +1] ----
    {
        const float* wpo = Wp + (size_t)o * 288 * 32;
        #pragma unroll 4
        for (int i = tid; i < 288 * 32; i += NTHR) {
            int j  = i >> 5;           // 0..287  (j = c*9 + k)
            int cp = i & 31;           // input channel
            float v = wpo[i];          // coalesced
            *(unsigned long long*)(wp_s + cp * WPSTR + j * 2) = pack2(v, v);
        }
    }

    // ---- Stage x halo tile: 32 channels x 10x10, col j(-1..8) at offset j+2 ----
    {
        const float* xb = x + (size_t)b * CIN * HDIM * WDIM;
        #pragma unroll 4
        for (int i = tid; i < CIN * 100; i += NTHR) {
            int c   = i / 100;
            int rr  = i - c * 100;
            int r   = rr / 10;
            int col = rr - r * 10;
            int yy = ty0 + r - 1;
            int xx = tx0 + col - 1;
            float v = 0.0f;
            if (yy >= 0 && yy < HDIM && xx >= 0 && xx < WDIM)
                v = xb[(c * HDIM + yy) * WDIM + xx];
            x_s[c * CSTR + r * XROW + col + 1] = v;
        }
    }
    __syncthreads();

    const int warp = tid >> 5;     // tile row (0..7)
    const int lane = tid & 31;     // lane = Cin index c

    // center pixel p=0 offset within a channel row block (even -> float2 aligned)
    const int centerBase = (1 + warp) * XROW + 2;

    // ---- Accumulators: packed pixel pairs. acc2[k][pp] = (p=2pp, p=2pp+1) ----
    unsigned long long acc2[KKN][4];
    {
        const float* bprow = bp + o * 288 + lane * KKN;
        #pragma unroll
        for (int k = 0; k < KKN; k++) {
            float bv = bprow[k];
            unsigned long long bb = pack2(bv, bv);
            #pragma unroll
            for (int pp = 0; pp < 4; pp++) acc2[k][pp] = bb;
        }
    }

    // ---- Mainloop: pred GEMM slice, K=32 over input channels cp ----
    const unsigned long long* wbase =
        (const unsigned long long*)wp_s + (size_t)lane * KKN;   // + cp*289 per row (578 words)
    #pragma unroll 4
    for (int cp = 0; cp < CIN; cp++) {
        unsigned long long xv2[4];
        const unsigned long long* xr =
            (const unsigned long long*)(x_s + cp * CSTR + centerBase);
        #pragma unroll
        for (int pp = 0; pp < 4; pp++) xv2[pp] = xr[pp];        // LDS.64 broadcast
        const unsigned long long* w2 = wbase + (size_t)cp * (WPSTR / 2);
        #pragma unroll
        for (int k = 0; k < KKN; k++) {
            unsigned long long w = w2[k];                        // LDS.64 conflict-free
            #pragma unroll
            for (int pp = 0; pp < 4; pp++)
                FFMA2(acc2[k][pp], w, xv2[pp], acc2[k][pp]);
        }
    }

    // ---- Normalize over Cin (= lanes): butterfly all-reduce of squares ----
    #pragma unroll
    for (int k = 0; k < KKN; k++) {
        #pragma unroll
        for (int pp = 0; pp < 4; pp++) {
            unsigned long long sq;
            FMUL2(sq, acc2[k][pp], acc2[k][pp]);
            float s0, s1;
            unpack2(sq, s0, s1);
            s0 += __shfl_xor_sync(0xffffffffu, s0, 16);
            s1 += __shfl_xor_sync(0xffffffffu, s1, 16);
            s0 += __shfl_xor_sync(0xffffffffu, s0, 8);
            s1 += __shfl_xor_sync(0xffffffffu, s1, 8);
            s0 += __shfl_xor_sync(0xffffffffu, s0, 4);
            s1 += __shfl_xor_sync(0xffffffffu, s1, 4);
            s0 += __shfl_xor_sync(0xffffffffu, s0, 2);
            s1 += __shfl_xor_sync(0xffffffffu, s1, 2);
            s0 += __shfl_xor_sync(0xffffffffu, s0, 1);
            s1 += __shfl_xor_sync(0xffffffffu, s1, 1);
            // v / max(sqrt(s),1e-12) == v * rsqrt(max(s,1e-24))
            float r0 = rsqrtf(fmaxf(s0, 1e-24f));
            float r1 = rsqrtf(fmaxf(s1, 1e-24f));
            unsigned long long rr = pack2(r0, r1);
            FMUL2(acc2[k][pp], acc2[k][pp], rr);
        }
    }

    // ---- Per-lane norm over k, patch contraction, dynamic bias, reduce ----
    const float wpb = Wp[(size_t)(9216 + o) * 32 + lane];  // dyn-bias predictor row
    const float bpo = bp[9216 + o];
    const float* xlane = x_s + lane * CSTR;

    #pragma unroll
    for (int pp = 0; pp < 4; pp++) {
        // packed sum of squares over k
        unsigned long long s2 = 0;
        {
            float z = 0.0f;
            s2 = pack2(z, z);
        }
        #pragma unroll
        for (int k = 0; k < KKN; k++)
            FFMA2(s2, acc2[k][pp], acc2[k][pp], s2);
        float sa, sb;
        unpack2(s2, sa, sb);
        float inva = rsqrtf(fmaxf(sa, 1e-24f));
        float invb = rsqrtf(fmaxf(sb, 1e-24f));

        float a[KKN][2];
        #pragma unroll
        for (int k = 0; k < KKN; k++) unpack2(acc2[k][pp], a[k][0], a[k][1]);

        #pragma unroll
        for (int h = 0; h < 2; h++) {
            int p = pp * 2 + h;
            float inv2 = h ? invb : inva;
            // dynamic bias partial: Wp[9216+o, lane] * x[lane, pixel]
            float t = wpb * xlane[centerBase + p];
            #pragma unroll
            for (int k = 0; k < KKN; k++) {
                int dy = k / 3, dx = k % 3;
                float pv = xlane[(warp + dy) * XROW + (p + dx + 1)];
                t = fmaf(a[k][h] * inv2, pv, t);
            }
            t += __shfl_xor_sync(0xffffffffu, t, 16);
            t += __shfl_xor_sync(0xffffffffu, t, 8);
            t += __shfl_xor_sync(0xffffffffu, t, 4);
            t += __shfl_xor_sync(0xffffffffu, t, 2);
            t += __shfl_xor_sync(0xffffffffu, t, 1);
            if (lane == 0) {
                int yy = ty0 + warp;
                int xx = tx0 + p;
                out[(((size_t)b * COUT + o) * HDIM + yy) * WDIM + xx] = t + bpo;
            }
        }
    }
}

extern "C" void kernel_launch(void* const* d_in, const int* in_sizes, int n_in,
                              void* d_out, int out_size)
{
    const float* x  = (const float*)d_in[0];   // (2, 32, 64, 64)
    const float* Wp = (const float*)d_in[1];   // (9248, 32)
    const float* bp = (const float*)d_in[2];   // (9248,)
    float* out = (float*)d_out;                // (2, 32, 64, 64)

    const size_t smem_bytes = SMEM_FLOATS * sizeof(float);   // 89600 B
    cudaFuncSetAttribute(dyn_conv_kernel,
                         cudaFuncAttributeMaxDynamicSharedMemorySize,
                         (int)smem_bytes);

    dim3 grid(WDIM / TILE, HDIM / TILE, 2 * COUT);  // (8, 8, 64)
    dyn_conv_kernel<<<grid, NTHR, smem_bytes>>>(x, Wp, bp, out);
}